// round 15
// baseline (speedup 1.0000x reference)
#include <cuda_runtime.h>
#include <math.h>
#include <stdint.h>

#define D 128
#define MAXN 2097152              // 2^21 >= 2,000,000 ; index fits in 21 bits
#define MAIN_BLOCKS 1184          // 8 CTAs/SM * 148 SMs
#define MAIN_THREADS 256
#define CAND_CAP 4096
#define REF_THREADS 256
#define ACC2_BLOCKS 296
#define ACC2_THREADS 256
#define LSEL_CAP 2080             // >= max selected per block (<= k = 2048)

// ---------------- device scratch (all zero-initialized at load) ----------
// Invariant: every kernel_launch call leaves counters/histogram back at zero
// (k_acc2 last block re-zeroes), so graph replays start from identical state.
__device__ float               g_y[MAXN];
__device__ unsigned long long  g_key64[MAXN];   // refined key, valid for current candidates only
__device__ unsigned            g_h1[2048];
__device__ unsigned            g_keyfloor;
__device__ int                 g_kk;
__device__ int                 g_candcnt;
__device__ int                 g_candidx[CAND_CAP];
__device__ unsigned long long  g_candkey[CAND_CAP];
__device__ unsigned long long  g_thresh;
__device__ float               g_partial2[ACC2_BLOCKS][D];
__device__ unsigned            g_done_main;
__device__ unsigned            g_done_ref;
__device__ unsigned            g_done_acc;

// monotonic key: larger float -> larger unsigned
__device__ __forceinline__ unsigned fkey(float f) {
    unsigned u = __float_as_uint(f);
    return (u & 0x80000000u) ? ~u : (u | 0x80000000u);
}

// ---------------- K1: scores + histogram + fused threshold scan ----------
__global__ void __launch_bounds__(MAIN_THREADS) k_main(
    const float* __restrict__ x, const float* __restrict__ v,
    const int* __restrict__ kp, int N)
{
    __shared__ unsigned sh[2048];
    for (int i = threadIdx.x; i < 2048; i += blockDim.x) sh[i] = 0u;

    const int lane = threadIdx.x & 31;
    const float4 v4 = __ldg(((const float4*)v) + lane);
    float sq = v4.x * v4.x;
    sq = fmaf(v4.y, v4.y, sq);
    sq = fmaf(v4.z, v4.z, sq);
    sq = fmaf(v4.w, v4.w, sq);
#pragma unroll
    for (int o = 16; o; o >>= 1) sq += __shfl_xor_sync(0xffffffffu, sq, o);
    const float invf = (float)(1.0 / sqrt((double)sq));
    __syncthreads();

    const int warp = blockIdx.x * (blockDim.x >> 5) + (threadIdx.x >> 5);
    const int nw   = gridDim.x * (blockDim.x >> 5);

    for (int r = warp; r < N; r += 4 * nw) {
        const int r1 = r + nw, r2 = r + 2 * nw, r3 = r + 3 * nw;
        float s0 = 0.f, s1 = 0.f, s2 = 0.f, s3 = 0.f;
        {
            float4 a = __ldcs((const float4*)(x + (size_t)r * D) + lane);
            s0 = a.x * v4.x; s0 = fmaf(a.y, v4.y, s0);
            s0 = fmaf(a.z, v4.z, s0); s0 = fmaf(a.w, v4.w, s0);
        }
        if (r1 < N) {
            float4 a = __ldcs((const float4*)(x + (size_t)r1 * D) + lane);
            s1 = a.x * v4.x; s1 = fmaf(a.y, v4.y, s1);
            s1 = fmaf(a.z, v4.z, s1); s1 = fmaf(a.w, v4.w, s1);
        }
        if (r2 < N) {
            float4 a = __ldcs((const float4*)(x + (size_t)r2 * D) + lane);
            s2 = a.x * v4.x; s2 = fmaf(a.y, v4.y, s2);
            s2 = fmaf(a.z, v4.z, s2); s2 = fmaf(a.w, v4.w, s2);
        }
        if (r3 < N) {
            float4 a = __ldcs((const float4*)(x + (size_t)r3 * D) + lane);
            s3 = a.x * v4.x; s3 = fmaf(a.y, v4.y, s3);
            s3 = fmaf(a.z, v4.z, s3); s3 = fmaf(a.w, v4.w, s3);
        }
#pragma unroll
        for (int o = 16; o; o >>= 1) {
            s0 += __shfl_down_sync(0xffffffffu, s0, o);
            s1 += __shfl_down_sync(0xffffffffu, s1, o);
            s2 += __shfl_down_sync(0xffffffffu, s2, o);
            s3 += __shfl_down_sync(0xffffffffu, s3, o);
        }
        if (lane == 0) {
            float y0 = s0 * invf;
            g_y[r] = y0; atomicAdd(&sh[fkey(y0) >> 21], 1u);
            if (r1 < N) { float y = s1 * invf; g_y[r1] = y; atomicAdd(&sh[fkey(y) >> 21], 1u); }
            if (r2 < N) { float y = s2 * invf; g_y[r2] = y; atomicAdd(&sh[fkey(y) >> 21], 1u); }
            if (r3 < N) { float y = s3 * invf; g_y[r3] = y; atomicAdd(&sh[fkey(y) >> 21], 1u); }
        }
    }
    __syncthreads();
    for (int i = threadIdx.x; i < 2048; i += blockDim.x) {
        unsigned c = sh[i];
        if (c) atomicAdd(&g_h1[i], c);
    }

    // ---- fused suffix-scan in the last-finishing block ----
    __threadfence();
    __shared__ bool lastb;
    if (threadIdx.x == 0)
        lastb = (atomicAdd(&g_done_main, 1u) == (unsigned)(gridDim.x - 1));
    __syncthreads();
    if (!lastb) return;
    if (threadIdx.x == 0) g_done_main = 0u;

    const int t = threadIdx.x;                 // 256 threads
    int kk = *kp;
    if (kk > N) kk = N;
    if (kk < 1) kk = 1;

    unsigned loc[8];
    unsigned sum = 0;
#pragma unroll
    for (int i = 0; i < 8; i++) {
        loc[i] = g_h1[2047 - (t * 8 + i)];
        sum += loc[i];
    }
    __syncthreads();
    unsigned* ps = sh;
    ps[t] = sum;
    __syncthreads();
    for (int off = 1; off < 256; off <<= 1) {
        unsigned add = (t >= off) ? ps[t - off] : 0u;
        __syncthreads();
        ps[t] += add;
        __syncthreads();
    }
    unsigned base = (t == 0) ? 0u : ps[t - 1];
    if (base < (unsigned)kk && ps[t] >= (unsigned)kk) {
        unsigned cum = base;
        int b = 0;
#pragma unroll
        for (int i = 0; i < 8; i++) {
            cum += loc[i];
            if (cum >= (unsigned)kk) { b = 2047 - (t * 8 + i); break; }
        }
        g_keyfloor = (unsigned)b << 21;
        g_kk = kk;
    }
    if (t == 0 && ps[255] < (unsigned)kk) {
        g_keyfloor = 0u;
        g_kk = kk;
    }
}

// ---------------- K2: collect candidates (front-batched MLP=4) -----------
__global__ void __launch_bounds__(256) k_cand(int N) {
    const unsigned kf = g_keyfloor;
    const int N4 = N >> 2;
    const float4* y4 = (const float4*)g_y;
    const int T = gridDim.x * blockDim.x;
    const int t = blockIdx.x * blockDim.x + threadIdx.x;

    const int i0 = t, i1 = t + T, i2 = t + 2 * T, i3 = t + 3 * T;
    float4 a0, a1, a2, a3;
    bool b0 = i0 < N4, b1 = i1 < N4, b2 = i2 < N4, b3 = i3 < N4;
    if (b0) a0 = y4[i0];
    if (b1) a1 = y4[i1];
    if (b2) a2 = y4[i2];
    if (b3) a3 = y4[i3];

#define CAND_TEST(val, idx) \
    if (fkey(val) >= kf) { int p = atomicAdd(&g_candcnt, 1); if (p < CAND_CAP) g_candidx[p] = (idx); }

    if (b0) { CAND_TEST(a0.x, 4*i0)   CAND_TEST(a0.y, 4*i0+1) CAND_TEST(a0.z, 4*i0+2) CAND_TEST(a0.w, 4*i0+3) }
    if (b1) { CAND_TEST(a1.x, 4*i1)   CAND_TEST(a1.y, 4*i1+1) CAND_TEST(a1.z, 4*i1+2) CAND_TEST(a1.w, 4*i1+3) }
    if (b2) { CAND_TEST(a2.x, 4*i2)   CAND_TEST(a2.y, 4*i2+1) CAND_TEST(a2.z, 4*i2+2) CAND_TEST(a2.w, 4*i2+3) }
    if (b3) { CAND_TEST(a3.x, 4*i3)   CAND_TEST(a3.y, 4*i3+1) CAND_TEST(a3.z, 4*i3+2) CAND_TEST(a3.w, 4*i3+3) }
#undef CAND_TEST

    if (blockIdx.x == 0 && threadIdx.x < 4) {
        int i = (N4 << 2) + threadIdx.x;
        if (i < N && fkey(g_y[i]) >= kf) {
            int p = atomicAdd(&g_candcnt, 1);
            if (p < CAND_CAP) g_candidx[p] = i;
        }
    }
}

// ---------------- K3: fp64 refine + FUSED radix select -------------------
__global__ void __launch_bounds__(REF_THREADS) k_refine(
    const float* __restrict__ x, const float* __restrict__ v)
{
    const int lane = threadIdx.x & 31;
    const int w    = blockIdx.x * (blockDim.x >> 5) + (threadIdx.x >> 5);
    const int nw   = gridDim.x * (blockDim.x >> 5);
    int nc = g_candcnt;
    if (nc > CAND_CAP) nc = CAND_CAP;
    const float4 v4 = __ldg(((const float4*)v) + lane);

    double vd = (double)v4.x * (double)v4.x
              + (double)v4.y * (double)v4.y
              + (double)v4.z * (double)v4.z
              + (double)v4.w * (double)v4.w;
#pragma unroll
    for (int o = 16; o; o >>= 1) vd += __shfl_xor_sync(0xffffffffu, vd, o);
    const double inv = 1.0 / sqrt(vd);

    for (int j = w; j < nc; j += nw) {
        const int r = g_candidx[j];
        float4 a = __ldg((const float4*)(x + (size_t)r * D) + lane);
        double s = (double)a.x * (double)v4.x
                 + (double)a.y * (double)v4.y
                 + (double)a.z * (double)v4.z
                 + (double)a.w * (double)v4.w;
#pragma unroll
        for (int o = 16; o; o >>= 1) s += __shfl_down_sync(0xffffffffu, s, o);
        if (lane == 0) {
            double yd = s * inv;
            long long bl = __double_as_longlong(yd);
            unsigned long long u = (unsigned long long)bl;
            unsigned long long m = (u >> 63) ? ~u : (u | 0x8000000000000000ull);
            unsigned long long key = (m & ~0x1FFFFFull)
                                   | (unsigned long long)(0x1FFFFFu - (unsigned)r);
            g_candkey[j] = key;   // slot order (multiset deterministic)
            g_key64[r]  = key;    // per-row (deterministic content)
        }
    }

    // ---- fused radix select in the last-finishing block ----
    __threadfence();
    __shared__ bool lastb;
    if (threadIdx.x == 0)
        lastb = (atomicAdd(&g_done_ref, 1u) == (unsigned)(gridDim.x - 1));
    __syncthreads();
    if (!lastb) return;
    if (threadIdx.x == 0) g_done_ref = 0u;

    __shared__ unsigned long long sk[CAND_CAP];
    __shared__ unsigned cnt[256];
    __shared__ unsigned long long s_prefix;
    __shared__ unsigned s_rank;
    __shared__ unsigned long long s_and[REF_THREADS / 32];
    __shared__ unsigned long long s_or[REF_THREADS / 32];

    int kk = g_kk; if (kk > nc) kk = nc;

    // load keys + per-thread AND/OR accumulate (keys are L2-hot)
    unsigned long long kand = ~0ull, kor = 0ull;
    for (int i = threadIdx.x; i < nc; i += REF_THREADS) {
        unsigned long long key = g_candkey[i];
        sk[i] = key;
        kand &= key; kor |= key;
    }
#pragma unroll
    for (int o = 16; o; o >>= 1) {
        kand &= __shfl_xor_sync(0xffffffffu, kand, o);
        kor  |= __shfl_xor_sync(0xffffffffu, kor, o);
    }
    if (lane == 0) {
        s_and[threadIdx.x >> 5] = kand;
        s_or[threadIdx.x >> 5]  = kor;
    }
    if (threadIdx.x == 0) { s_prefix = 0ull; s_rank = (unsigned)kk; }
    __syncthreads();
    if (threadIdx.x == 0) {
        unsigned long long a = ~0ull, o = 0ull;
        for (int i = 0; i < REF_THREADS / 32; i++) { a &= s_and[i]; o |= s_or[i]; }
        s_and[0] = a; s_or[0] = o;
    }
    __syncthreads();
    const unsigned long long all_and = s_and[0];
    const unsigned long long all_or  = s_or[0];

    for (int pass = 0; pass < 8; pass++) {
        const int shift = 56 - 8 * pass;
        const unsigned ba = (unsigned)(all_and >> shift) & 255u;
        const unsigned bo = (unsigned)(all_or  >> shift) & 255u;
        if (ba == bo) {
            if (threadIdx.x == 0)
                s_prefix |= ((unsigned long long)ba << shift);
            __syncthreads();
            continue;
        }
        const unsigned long long pmask =
            (pass == 0) ? 0ull : (~0ull << (unsigned)(shift + 8));
        if (threadIdx.x < 256) cnt[threadIdx.x] = 0u;
        __syncthreads();
        const unsigned long long pref = s_prefix;
        for (int i = threadIdx.x; i < nc; i += REF_THREADS) {
            unsigned long long key = sk[i];
            if ((key & pmask) == pref)
                atomicAdd(&cnt[(unsigned)(key >> shift) & 255u], 1u);
        }
        __syncthreads();
        if (threadIdx.x < 32) {
            unsigned loc[8];
            unsigned s = 0;
#pragma unroll
            for (int i = 0; i < 8; i++) {
                loc[i] = cnt[255 - (lane * 8 + i)];
                s += loc[i];
            }
            unsigned tot = s;
#pragma unroll
            for (int o = 1; o < 32; o <<= 1) {
                unsigned a = __shfl_up_sync(0xffffffffu, tot, o);
                if (lane >= o) tot += a;
            }
            const unsigned base = tot - s;
            const unsigned r = s_rank;        // read BEFORE any lane writes
            __syncwarp();
            if (base < r && tot >= r) {       // exactly one lane matches
                unsigned cum = base;
#pragma unroll
                for (int i = 0; i < 8; i++) {
                    cum += loc[i];
                    if (cum >= r) {
                        unsigned d = 255u - (unsigned)(lane * 8 + i);
                        s_prefix = pref | ((unsigned long long)d << shift);
                        s_rank   = r - (cum - loc[i]);
                        break;
                    }
                }
            }
        }
        __syncthreads();
    }
    if (threadIdx.x == 0) g_thresh = s_prefix;
}

// ---------------- K4: deterministic COALESCED scan-select + gather-reduce -
__global__ void __launch_bounds__(ACC2_THREADS) k_acc2(
    const float* __restrict__ x, float* __restrict__ out, int N)
{
    __shared__ int      lrow[LSEL_CAP];
    __shared__ float    lgate[LSEL_CAP];
    __shared__ unsigned tcnt[ACC2_THREADS];
    __shared__ float    combine[ACC2_THREADS];
    __shared__ bool     last;

    const int chunk = (N + gridDim.x - 1) / (int)gridDim.x;   // <= 7086 < 32*256
    const int r0 = blockIdx.x * chunk;
    const int r1 = min(N, r0 + chunk);

    const unsigned kf = g_keyfloor;
    const unsigned long long T = g_thresh;

    // pass 1: coalesced scan (thread t reads rows r0+t, r0+t+256, ...)
    unsigned mask = 0u;
    unsigned c = 0u;
    {
        int i = 0;
        for (int r = r0 + threadIdx.x; r < r1; r += ACC2_THREADS, i++) {
            float y = g_y[r];
            if (fkey(y) >= kf && g_key64[r] >= T) { mask |= (1u << i); c++; }
        }
    }
    tcnt[threadIdx.x] = c;
    __syncthreads();
    for (int off = 1; off < ACC2_THREADS; off <<= 1) {
        unsigned add = (threadIdx.x >= (unsigned)off) ? tcnt[threadIdx.x - off] : 0u;
        __syncthreads();
        tcnt[threadIdx.x] += add;
        __syncthreads();
    }
    unsigned pos = (threadIdx.x == 0) ? 0u : tcnt[threadIdx.x - 1];
    const int m = (int)tcnt[ACC2_THREADS - 1];
    // pass 2: write selected rows (fixed (i,tid) order — deterministic; L2-hot)
    if (mask) {
        int i = 0;
        for (int r = r0 + threadIdx.x; r < r1; r += ACC2_THREADS, i++) {
            if (mask & (1u << i)) {
                float y = g_y[r];
                lrow[pos]  = r;
                lgate[pos] = 1.f / (1.f + expf(-y));
                pos++;
            }
        }
    }
    __syncthreads();

    // gather-reduce: column c, two row-interleaved halves
    const int col = threadIdx.x & 127;
    float acc = 0.f;
    for (int j = (threadIdx.x >> 7); j < m; j += 2)
        acc = fmaf(lgate[j], __ldg(x + (size_t)lrow[j] * D + col), acc);
    combine[threadIdx.x] = acc;
    __syncthreads();
    if (threadIdx.x < 128)
        g_partial2[blockIdx.x][threadIdx.x] =
            combine[threadIdx.x] + combine[threadIdx.x + 128];
    __threadfence();
    __syncthreads();
    if (threadIdx.x == 0)
        last = (atomicAdd(&g_done_acc, 1u) == (unsigned)(gridDim.x - 1));
    __syncthreads();
    if (last) {
        if (threadIdx.x < 128) {
            float s = 0.f;
            for (int b = 0; b < ACC2_BLOCKS; ++b) s += g_partial2[b][threadIdx.x];
            out[threadIdx.x] = s;
        }
        // restore zeroed state for the next graph replay
        for (int i = threadIdx.x; i < 2048; i += ACC2_THREADS) g_h1[i] = 0u;
        if (threadIdx.x == 0) { g_candcnt = 0; g_done_acc = 0u; }
    }
}

// ---------------- launch ----------------
extern "C" void kernel_launch(void* const* d_in, const int* in_sizes, int n_in,
                              void* d_out, int out_size) {
    const float* x  = (const float*)d_in[0];
    const float* v  = (const float*)d_in[1];
    const int*   kp = (const int*)d_in[2];
    float* out = (float*)d_out;
    int N = in_sizes[0] / D;
    if (N > MAXN) N = MAXN;

    k_main  <<<MAIN_BLOCKS, MAIN_THREADS>>>(x, v, kp, N);
    k_cand  <<<512, 256>>>(N);
    k_refine<<<128, REF_THREADS>>>(x, v);
    k_acc2  <<<ACC2_BLOCKS, ACC2_THREADS>>>(x, out, N);
    (void)n_in; (void)out_size;
}

// round 16
// speedup vs baseline: 1.2193x; 1.2193x over previous
#include <cuda_runtime.h>
#include <math.h>
#include <stdint.h>

#define D 128
#define MAXN 2097152              // 2^21 >= 2,000,000 ; index fits in 21 bits
#define MAIN_BLOCKS 1184          // 8 CTAs/SM * 148 SMs
#define MAIN_THREADS 256
#define CAND_CAP 4096
#define SEL_THREADS 512
#define ACC2_BLOCKS 592
#define ACC2_THREADS 256
#define LSEL_CAP 2080             // >= max selected per block (<= k = 2048)

// ---------------- device scratch (all zero-initialized at load) ----------
// Invariant: every kernel_launch call leaves counters/histogram back at zero
// (k_acc2 last block re-zeroes), so graph replays start from identical state.
__device__ float               g_y[MAXN];
__device__ unsigned long long  g_key64[MAXN];   // refined key, valid for current candidates only
__device__ unsigned            g_h1[2048];
__device__ unsigned            g_keyfloor;
__device__ int                 g_kk;
__device__ int                 g_candcnt;
__device__ int                 g_candidx[CAND_CAP];
__device__ unsigned long long  g_candkey[CAND_CAP];
__device__ unsigned long long  g_thresh;
__device__ float               g_partial2[ACC2_BLOCKS][D];
__device__ unsigned            g_done_main;
__device__ unsigned            g_done_acc;

// monotonic key: larger float -> larger unsigned
__device__ __forceinline__ unsigned fkey(float f) {
    unsigned u = __float_as_uint(f);
    return (u & 0x80000000u) ? ~u : (u | 0x80000000u);
}

// ---------------- K1: scores + histogram + fused threshold scan ----------
__global__ void __launch_bounds__(MAIN_THREADS) k_main(
    const float* __restrict__ x, const float* __restrict__ v,
    const int* __restrict__ kp, int N)
{
    __shared__ unsigned sh[2048];
    for (int i = threadIdx.x; i < 2048; i += blockDim.x) sh[i] = 0u;

    const int lane = threadIdx.x & 31;
    const float4 v4 = __ldg(((const float4*)v) + lane);
    float sq = v4.x * v4.x;
    sq = fmaf(v4.y, v4.y, sq);
    sq = fmaf(v4.z, v4.z, sq);
    sq = fmaf(v4.w, v4.w, sq);
#pragma unroll
    for (int o = 16; o; o >>= 1) sq += __shfl_xor_sync(0xffffffffu, sq, o);
    const float invf = (float)(1.0 / sqrt((double)sq));
    __syncthreads();

    const int warp = blockIdx.x * (blockDim.x >> 5) + (threadIdx.x >> 5);
    const int nw   = gridDim.x * (blockDim.x >> 5);

    for (int r = warp; r < N; r += 4 * nw) {
        const int r1 = r + nw, r2 = r + 2 * nw, r3 = r + 3 * nw;
        float s0 = 0.f, s1 = 0.f, s2 = 0.f, s3 = 0.f;
        {
            float4 a = __ldcs((const float4*)(x + (size_t)r * D) + lane);
            s0 = a.x * v4.x; s0 = fmaf(a.y, v4.y, s0);
            s0 = fmaf(a.z, v4.z, s0); s0 = fmaf(a.w, v4.w, s0);
        }
        if (r1 < N) {
            float4 a = __ldcs((const float4*)(x + (size_t)r1 * D) + lane);
            s1 = a.x * v4.x; s1 = fmaf(a.y, v4.y, s1);
            s1 = fmaf(a.z, v4.z, s1); s1 = fmaf(a.w, v4.w, s1);
        }
        if (r2 < N) {
            float4 a = __ldcs((const float4*)(x + (size_t)r2 * D) + lane);
            s2 = a.x * v4.x; s2 = fmaf(a.y, v4.y, s2);
            s2 = fmaf(a.z, v4.z, s2); s2 = fmaf(a.w, v4.w, s2);
        }
        if (r3 < N) {
            float4 a = __ldcs((const float4*)(x + (size_t)r3 * D) + lane);
            s3 = a.x * v4.x; s3 = fmaf(a.y, v4.y, s3);
            s3 = fmaf(a.z, v4.z, s3); s3 = fmaf(a.w, v4.w, s3);
        }
#pragma unroll
        for (int o = 16; o; o >>= 1) {
            s0 += __shfl_down_sync(0xffffffffu, s0, o);
            s1 += __shfl_down_sync(0xffffffffu, s1, o);
            s2 += __shfl_down_sync(0xffffffffu, s2, o);
            s3 += __shfl_down_sync(0xffffffffu, s3, o);
        }
        if (lane == 0) {
            float y0 = s0 * invf;
            g_y[r] = y0; atomicAdd(&sh[fkey(y0) >> 21], 1u);
            if (r1 < N) { float y = s1 * invf; g_y[r1] = y; atomicAdd(&sh[fkey(y) >> 21], 1u); }
            if (r2 < N) { float y = s2 * invf; g_y[r2] = y; atomicAdd(&sh[fkey(y) >> 21], 1u); }
            if (r3 < N) { float y = s3 * invf; g_y[r3] = y; atomicAdd(&sh[fkey(y) >> 21], 1u); }
        }
    }
    __syncthreads();
    for (int i = threadIdx.x; i < 2048; i += blockDim.x) {
        unsigned c = sh[i];
        if (c) atomicAdd(&g_h1[i], c);
    }

    // ---- fused suffix-scan in the last-finishing block ----
    __threadfence();
    __shared__ bool lastb;
    if (threadIdx.x == 0)
        lastb = (atomicAdd(&g_done_main, 1u) == (unsigned)(gridDim.x - 1));
    __syncthreads();
    if (!lastb) return;
    if (threadIdx.x == 0) g_done_main = 0u;

    const int t = threadIdx.x;                 // 256 threads
    int kk = *kp;
    if (kk > N) kk = N;
    if (kk < 1) kk = 1;

    unsigned loc[8];
    unsigned sum = 0;
#pragma unroll
    for (int i = 0; i < 8; i++) {
        loc[i] = g_h1[2047 - (t * 8 + i)];
        sum += loc[i];
    }
    __syncthreads();
    unsigned* ps = sh;
    ps[t] = sum;
    __syncthreads();
    for (int off = 1; off < 256; off <<= 1) {
        unsigned add = (t >= off) ? ps[t - off] : 0u;
        __syncthreads();
        ps[t] += add;
        __syncthreads();
    }
    unsigned base = (t == 0) ? 0u : ps[t - 1];
    if (base < (unsigned)kk && ps[t] >= (unsigned)kk) {
        unsigned cum = base;
        int b = 0;
#pragma unroll
        for (int i = 0; i < 8; i++) {
            cum += loc[i];
            if (cum >= (unsigned)kk) { b = 2047 - (t * 8 + i); break; }
        }
        g_keyfloor = (unsigned)b << 21;
        g_kk = kk;
    }
    if (t == 0 && ps[255] < (unsigned)kk) {
        g_keyfloor = 0u;
        g_kk = kk;
    }
}

// ---------------- K2: collect candidates (front-batched MLP=4) -----------
__global__ void __launch_bounds__(256) k_cand(int N) {
    const unsigned kf = g_keyfloor;
    const int N4 = N >> 2;
    const float4* y4 = (const float4*)g_y;
    const int T = gridDim.x * blockDim.x;
    const int t = blockIdx.x * blockDim.x + threadIdx.x;

    const int i0 = t, i1 = t + T, i2 = t + 2 * T, i3 = t + 3 * T;
    float4 a0, a1, a2, a3;
    bool b0 = i0 < N4, b1 = i1 < N4, b2 = i2 < N4, b3 = i3 < N4;
    if (b0) a0 = y4[i0];
    if (b1) a1 = y4[i1];
    if (b2) a2 = y4[i2];
    if (b3) a3 = y4[i3];

#define CAND_TEST(val, idx) \
    if (fkey(val) >= kf) { int p = atomicAdd(&g_candcnt, 1); if (p < CAND_CAP) g_candidx[p] = (idx); }

    if (b0) { CAND_TEST(a0.x, 4*i0)   CAND_TEST(a0.y, 4*i0+1) CAND_TEST(a0.z, 4*i0+2) CAND_TEST(a0.w, 4*i0+3) }
    if (b1) { CAND_TEST(a1.x, 4*i1)   CAND_TEST(a1.y, 4*i1+1) CAND_TEST(a1.z, 4*i1+2) CAND_TEST(a1.w, 4*i1+3) }
    if (b2) { CAND_TEST(a2.x, 4*i2)   CAND_TEST(a2.y, 4*i2+1) CAND_TEST(a2.z, 4*i2+2) CAND_TEST(a2.w, 4*i2+3) }
    if (b3) { CAND_TEST(a3.x, 4*i3)   CAND_TEST(a3.y, 4*i3+1) CAND_TEST(a3.z, 4*i3+2) CAND_TEST(a3.w, 4*i3+3) }
#undef CAND_TEST

    if (blockIdx.x == 0 && threadIdx.x < 4) {
        int i = (N4 << 2) + threadIdx.x;
        if (i < N && fkey(g_y[i]) >= kf) {
            int p = atomicAdd(&g_candcnt, 1);
            if (p < CAND_CAP) g_candidx[p] = i;
        }
    }
}

// ---------------- K3: fp64 refine; write slot key + per-row key ----------
__global__ void k_refine(const float* __restrict__ x, const float* __restrict__ v) {
    const int lane = threadIdx.x & 31;
    const int w    = blockIdx.x * (blockDim.x >> 5) + (threadIdx.x >> 5);
    const int nw   = gridDim.x * (blockDim.x >> 5);
    int nc = g_candcnt;
    if (nc > CAND_CAP) nc = CAND_CAP;
    const float4 v4 = __ldg(((const float4*)v) + lane);

    double vd = (double)v4.x * (double)v4.x
              + (double)v4.y * (double)v4.y
              + (double)v4.z * (double)v4.z
              + (double)v4.w * (double)v4.w;
#pragma unroll
    for (int o = 16; o; o >>= 1) vd += __shfl_xor_sync(0xffffffffu, vd, o);
    const double inv = 1.0 / sqrt(vd);

    for (int j = w; j < nc; j += nw) {
        const int r = g_candidx[j];
        float4 a = __ldg((const float4*)(x + (size_t)r * D) + lane);
        double s = (double)a.x * (double)v4.x
                 + (double)a.y * (double)v4.y
                 + (double)a.z * (double)v4.z
                 + (double)a.w * (double)v4.w;
#pragma unroll
        for (int o = 16; o; o >>= 1) s += __shfl_down_sync(0xffffffffu, s, o);
        if (lane == 0) {
            double yd = s * inv;
            long long bl = __double_as_longlong(yd);
            unsigned long long u = (unsigned long long)bl;
            unsigned long long m = (u >> 63) ? ~u : (u | 0x8000000000000000ull);
            unsigned long long key = (m & ~0x1FFFFFull)
                                   | (unsigned long long)(0x1FFFFFu - (unsigned)r);
            g_candkey[j] = key;   // slot order (multiset deterministic)
            g_key64[r]  = key;    // per-row (deterministic content)
        }
    }
}

// ---------------- K4: radix select; skip globally-constant bytes ---------
__global__ void __launch_bounds__(SEL_THREADS) k_select() {
    __shared__ unsigned long long sk[CAND_CAP];
    __shared__ unsigned cnt[256];
    __shared__ unsigned long long s_prefix;
    __shared__ unsigned s_rank;
    __shared__ unsigned long long s_and[SEL_THREADS / 32];
    __shared__ unsigned long long s_or[SEL_THREADS / 32];

    int nc = g_candcnt; if (nc > CAND_CAP) nc = CAND_CAP;
    int kk = g_kk;      if (kk > nc) kk = nc;

    // load keys + per-thread AND/OR accumulate
    unsigned long long kand = ~0ull, kor = 0ull;
    for (int i = threadIdx.x; i < nc; i += SEL_THREADS) {
        unsigned long long key = g_candkey[i];
        sk[i] = key;
        kand &= key; kor |= key;
    }
#pragma unroll
    for (int o = 16; o; o >>= 1) {
        kand &= __shfl_xor_sync(0xffffffffu, kand, o);
        kor  |= __shfl_xor_sync(0xffffffffu, kor, o);
    }
    if ((threadIdx.x & 31) == 0) {
        s_and[threadIdx.x >> 5] = kand;
        s_or[threadIdx.x >> 5]  = kor;
    }
    if (threadIdx.x == 0) { s_prefix = 0ull; s_rank = (unsigned)kk; }
    __syncthreads();
    if (threadIdx.x == 0) {
        unsigned long long a = ~0ull, o = 0ull;
        for (int i = 0; i < SEL_THREADS / 32; i++) { a &= s_and[i]; o |= s_or[i]; }
        s_and[0] = a; s_or[0] = o;
    }
    __syncthreads();
    const unsigned long long all_and = s_and[0];
    const unsigned long long all_or  = s_or[0];

    for (int pass = 0; pass < 8; pass++) {
        const int shift = 56 - 8 * pass;
        const unsigned ba = (unsigned)(all_and >> shift) & 255u;
        const unsigned bo = (unsigned)(all_or  >> shift) & 255u;
        if (ba == bo) {
            // byte constant across ALL keys -> constant in any subset: skip pass
            if (threadIdx.x == 0)
                s_prefix |= ((unsigned long long)ba << shift);
            __syncthreads();
            continue;
        }
        const unsigned long long pmask =
            (pass == 0) ? 0ull : (~0ull << (unsigned)(shift + 8));
        if (threadIdx.x < 256) cnt[threadIdx.x] = 0u;
        __syncthreads();
        const unsigned long long pref = s_prefix;
        for (int i = threadIdx.x; i < nc; i += SEL_THREADS) {
            unsigned long long key = sk[i];
            if ((key & pmask) == pref)
                atomicAdd(&cnt[(unsigned)(key >> shift) & 255u], 1u);
        }
        __syncthreads();
        // warp 0: suffix sums over descending digits + crossing search, shfl only
        if (threadIdx.x < 32) {
            const int lane = threadIdx.x;
            unsigned loc[8];
            unsigned s = 0;
#pragma unroll
            for (int i = 0; i < 8; i++) {
                loc[i] = cnt[255 - (lane * 8 + i)];
                s += loc[i];
            }
            unsigned tot = s;
#pragma unroll
            for (int o = 1; o < 32; o <<= 1) {
                unsigned a = __shfl_up_sync(0xffffffffu, tot, o);
                if (lane >= o) tot += a;
            }
            const unsigned base = tot - s;
            const unsigned r = s_rank;        // read BEFORE any lane writes
            __syncwarp();
            if (base < r && tot >= r) {       // exactly one lane matches
                unsigned cum = base;
#pragma unroll
                for (int i = 0; i < 8; i++) {
                    cum += loc[i];
                    if (cum >= r) {
                        unsigned d = 255u - (unsigned)(lane * 8 + i);
                        s_prefix = pref | ((unsigned long long)d << shift);
                        s_rank   = r - (cum - loc[i]);
                        break;
                    }
                }
            }
        }
        __syncthreads();
    }
    if (threadIdx.x == 0) g_thresh = s_prefix;
}

// ---------------- K5: vectorized scan-select + gather-reduce (occ 50%) ----
__global__ void __launch_bounds__(ACC2_THREADS) k_acc2(
    const float* __restrict__ x, float* __restrict__ out, int N)
{
    __shared__ int      lrow[LSEL_CAP];
    __shared__ float    lgate[LSEL_CAP];
    __shared__ unsigned tcnt[ACC2_THREADS];
    __shared__ float    combine[ACC2_THREADS];
    __shared__ bool     last;

    // chunk rounded to multiple of 4 so float4 reads stay aligned
    int chunk = (N + gridDim.x - 1) / (int)gridDim.x;
    chunk = (chunk + 3) & ~3;                     // <= 3380 < 8*1024 -> i < 4
    const int r0 = blockIdx.x * chunk;
    const int r1 = min(N, r0 + chunk);

    const unsigned kf = g_keyfloor;
    const unsigned long long T = g_thresh;

    // pass 1: vectorized coalesced scan; thread t covers [r0+4t, r0+4t+3], +1024
    unsigned mask = 0u;
    unsigned c = 0u;
    {
        int i = 0;
        for (int base = r0 + threadIdx.x * 4; base < r1;
             base += ACC2_THREADS * 4, i++) {
            if (base + 3 < r1) {
                float4 yv = *(const float4*)(g_y + base);
                if (fkey(yv.x) >= kf && g_key64[base]     >= T) { mask |= 1u << (4*i);     c++; }
                if (fkey(yv.y) >= kf && g_key64[base + 1] >= T) { mask |= 1u << (4*i + 1); c++; }
                if (fkey(yv.z) >= kf && g_key64[base + 2] >= T) { mask |= 1u << (4*i + 2); c++; }
                if (fkey(yv.w) >= kf && g_key64[base + 3] >= T) { mask |= 1u << (4*i + 3); c++; }
            } else {
                for (int j = 0; base + j < r1; j++) {
                    float y = g_y[base + j];
                    if (fkey(y) >= kf && g_key64[base + j] >= T) {
                        mask |= 1u << (4*i + j); c++;
                    }
                }
            }
        }
    }
    tcnt[threadIdx.x] = c;
    __syncthreads();
    for (int off = 1; off < ACC2_THREADS; off <<= 1) {
        unsigned add = (threadIdx.x >= (unsigned)off) ? tcnt[threadIdx.x - off] : 0u;
        __syncthreads();
        tcnt[threadIdx.x] += add;
        __syncthreads();
    }
    unsigned pos = (threadIdx.x == 0) ? 0u : tcnt[threadIdx.x - 1];
    const int m = (int)tcnt[ACC2_THREADS - 1];
    // pass 2: write selected rows (fixed (i,tid,sub) order — deterministic)
    if (mask) {
        int i = 0;
        for (int base = r0 + threadIdx.x * 4; base < r1;
             base += ACC2_THREADS * 4, i++) {
#pragma unroll
            for (int j = 0; j < 4; j++) {
                if (mask & (1u << (4*i + j))) {
                    int r = base + j;
                    float y = g_y[r];
                    lrow[pos]  = r;
                    lgate[pos] = 1.f / (1.f + expf(-y));
                    pos++;
                }
            }
        }
    }
    __syncthreads();

    // gather-reduce: column c, two row-interleaved halves
    const int col = threadIdx.x & 127;
    float acc = 0.f;
    for (int j = (threadIdx.x >> 7); j < m; j += 2)
        acc = fmaf(lgate[j], __ldg(x + (size_t)lrow[j] * D + col), acc);
    combine[threadIdx.x] = acc;
    __syncthreads();
    if (threadIdx.x < 128)
        g_partial2[blockIdx.x][threadIdx.x] =
            combine[threadIdx.x] + combine[threadIdx.x + 128];
    __threadfence();
    __syncthreads();
    if (threadIdx.x == 0)
        last = (atomicAdd(&g_done_acc, 1u) == (unsigned)(gridDim.x - 1));
    __syncthreads();
    if (last) {
        // final reduce over 592 partials: 256 threads, 2-way block split per col
        const int half = threadIdx.x >> 7;
        float s = 0.f;
        for (int b = half; b < ACC2_BLOCKS; b += 2) s += g_partial2[b][col];
        combine[threadIdx.x] = s;
        __syncthreads();
        if (threadIdx.x < 128)
            out[threadIdx.x] = combine[threadIdx.x] + combine[threadIdx.x + 128];
        // restore zeroed state for the next graph replay
        for (int i = threadIdx.x; i < 2048; i += ACC2_THREADS) g_h1[i] = 0u;
        if (threadIdx.x == 0) { g_candcnt = 0; g_done_acc = 0u; }
    }
}

// ---------------- launch ----------------
extern "C" void kernel_launch(void* const* d_in, const int* in_sizes, int n_in,
                              void* d_out, int out_size) {
    const float* x  = (const float*)d_in[0];
    const float* v  = (const float*)d_in[1];
    const int*   kp = (const int*)d_in[2];
    float* out = (float*)d_out;
    int N = in_sizes[0] / D;
    if (N > MAXN) N = MAXN;

    k_main  <<<MAIN_BLOCKS, MAIN_THREADS>>>(x, v, kp, N);
    k_cand  <<<512, 256>>>(N);
    k_refine<<<128, 256>>>(x, v);
    k_select<<<1, SEL_THREADS>>>();
    k_acc2  <<<ACC2_BLOCKS, ACC2_THREADS>>>(x, out, N);
    (void)n_in; (void)out_size;
}